// round 8
// baseline (speedup 1.0000x reference)
#include <cuda_runtime.h>
#include <math.h>

// ---------------------------------------------------------------- constants
#define BB 64
#define NN 197
#define CC 768
#define HH 12
#define HD 64
#define C3 2304
#define C4 3072
#define MR (BB*NN)        /* 12608 rows */
#define BH (BB*HH)        /* 768 (b,h) pairs */
#define LN_EPS 1e-5f

// ---------------------------------------------------------------- scratch
// (device globals: allocation APIs are forbidden; this is the sanctioned path)
__device__ __align__(16) float g_xn  [(size_t)MR * CC];   //  38.7 MB  LN1 out
__device__ __align__(16) float g_qkv [(size_t)MR * C3];   // 116.2 MB  qkv (post-policy)
__device__ __align__(16) float g_attn[(size_t)BH * NN * NN]; // 119.2 MB softmaxed attn
__device__ __align__(16) float g_xo  [(size_t)MR * CC];   //  38.7 MB  gathered attn @ V
__device__ __align__(16) float g_x2  [(size_t)MR * CC];   //  38.7 MB  residual-1 out
__device__ __align__(16) float g_ln2 [(size_t)MR * CC];   //  38.7 MB  LN2 out
__device__ __align__(16) float g_fc1 [(size_t)MR * C4];   // 155.0 MB  gelu(fc1)
__device__ int   g_rowmap[MR];   // per output row: source token idx in [0,196], or -1 (zero row)
__device__ float g_pol   [MR];   // per output row policy (0/1)

// ---------------------------------------------------------------- LayerNorm
// mode 0: Xin -> g_xn ;  mode 1: g_x2 -> g_ln2
__global__ void ln_kernel(const float* __restrict__ Xin,
                          const float* __restrict__ gam,
                          const float* __restrict__ bet,
                          int mode)
{
    const float* X = (mode == 0) ? Xin : g_x2;
    float*       Y = (mode == 0) ? g_xn : g_ln2;

    __shared__ float red[40];
    int row = blockIdx.x;
    int t   = threadIdx.x;
    const float* x = X + (size_t)row * CC;

    float v0 = x[t], v1 = x[t + 256], v2 = x[t + 512];

    // ---- mean
    float s = v0 + v1 + v2;
    #pragma unroll
    for (int o = 16; o > 0; o >>= 1) s += __shfl_xor_sync(0xffffffffu, s, o);
    if ((t & 31) == 0) red[t >> 5] = s;
    __syncthreads();
    if (t < 32) {
        float r = (t < 8) ? red[t] : 0.0f;
        #pragma unroll
        for (int o = 4; o > 0; o >>= 1) r += __shfl_xor_sync(0xffffffffu, r, o);
        if (t == 0) red[32] = r;
    }
    __syncthreads();
    float mean = red[32] * (1.0f / 768.0f);
    __syncthreads();

    // ---- variance
    float d0 = v0 - mean, d1 = v1 - mean, d2 = v2 - mean;
    s = d0 * d0 + d1 * d1 + d2 * d2;
    #pragma unroll
    for (int o = 16; o > 0; o >>= 1) s += __shfl_xor_sync(0xffffffffu, s, o);
    if ((t & 31) == 0) red[t >> 5] = s;
    __syncthreads();
    if (t < 32) {
        float r = (t < 8) ? red[t] : 0.0f;
        #pragma unroll
        for (int o = 4; o > 0; o >>= 1) r += __shfl_xor_sync(0xffffffffu, r, o);
        if (t == 0) red[33] = r;
    }
    __syncthreads();
    float var  = red[33] * (1.0f / 768.0f);
    float rstd = 1.0f / sqrtf(var + LN_EPS);

    float* y = Y + (size_t)row * CC;
    y[t]       = d0 * rstd * gam[t]       + bet[t];
    y[t + 256] = d1 * rstd * gam[t + 256] + bet[t + 256];
    y[t + 512] = d2 * rstd * gam[t + 512] + bet[t + 512];
}

// ---------------------------------------------------------------- SGEMM 128x128x16
// MODE 0: g_xn  @ Bm(768x2304) -> g_qkv ; epi: * policy[row]          (aux=policy)
// MODE 1: g_xo  @ Bm(768x768)  -> g_x2  ; epi: xgather + (acc+b)*pol  (aux=x input)
// MODE 2: g_ln2 @ Bm(768x3072) -> g_fc1 ; epi: exact GELU(acc+b)
// MODE 3: g_fc1 @ Bm(3072x768) -> Cext  ; epi: (g_x2 + acc + b)*pol
template <int MODE>
__global__ __launch_bounds__(256)
void sgemm_k(const float* __restrict__ Bm,
             const float* __restrict__ bias,
             const float* __restrict__ aux,
             float* __restrict__ Cext)
{
    constexpr int Nn = (MODE == 0) ? C3 : (MODE == 2) ? C4 : CC;
    constexpr int Kk = (MODE == 3) ? C4 : CC;
    const float* A =
        (MODE == 0) ? g_xn : (MODE == 1) ? g_xo : (MODE == 2) ? g_ln2 : g_fc1;
    float* Cout =
        (MODE == 0) ? g_qkv : (MODE == 1) ? g_x2 : (MODE == 2) ? g_fc1 : Cext;

    __shared__ float As[16][128];
    __shared__ float Bs[16][128];

    int tid  = threadIdx.x;
    int bx   = blockIdx.x;          // N tile
    int row0 = blockIdx.y * 128;    // M tile
    int tx   = tid & 15;
    int ty   = tid >> 4;

    int a_r = tid >> 2;             // 0..63
    int a_c = (tid & 3) << 2;       // 0,4,8,12
    int b_r = tid >> 5;             // 0..7
    int b_c = (tid & 31) << 2;      // 0..124

    float acc[8][8];
    #pragma unroll
    for (int i = 0; i < 8; i++)
        #pragma unroll
        for (int j = 0; j < 8; j++) acc[i][j] = 0.0f;

    for (int k0 = 0; k0 < Kk; k0 += 16) {
        #pragma unroll
        for (int p = 0; p < 2; p++) {
            int r = row0 + a_r + p * 64;
            float4 v = (r < MR)
                ? *(const float4*)(A + (size_t)r * Kk + k0 + a_c)
                : make_float4(0.f, 0.f, 0.f, 0.f);
            As[a_c + 0][a_r + p * 64] = v.x;
            As[a_c + 1][a_r + p * 64] = v.y;
            As[a_c + 2][a_r + p * 64] = v.z;
            As[a_c + 3][a_r + p * 64] = v.w;
        }
        #pragma unroll
        for (int p = 0; p < 2; p++) {
            int kr = k0 + b_r + p * 8;
            *(float4*)(&Bs[b_r + p * 8][b_c]) =
                *(const float4*)(Bm + (size_t)kr * Nn + bx * 128 + b_c);
        }
        __syncthreads();

        #pragma unroll
        for (int k = 0; k < 16; k++) {
            float af[8], bf[8];
            *(float4*)(af)     = *(const float4*)(&As[k][ty * 4]);
            *(float4*)(af + 4) = *(const float4*)(&As[k][ty * 4 + 64]);
            *(float4*)(bf)     = *(const float4*)(&Bs[k][tx * 4]);
            *(float4*)(bf + 4) = *(const float4*)(&Bs[k][tx * 4 + 64]);
            #pragma unroll
            for (int i = 0; i < 8; i++)
                #pragma unroll
                for (int j = 0; j < 8; j++)
                    acc[i][j] = fmaf(af[i], bf[j], acc[i][j]);
        }
        __syncthreads();
    }

    #pragma unroll
    for (int i = 0; i < 8; i++) {
        int row = row0 + ty * 4 + ((i & 4) ? 64 : 0) + (i & 3);
        if (row >= MR) continue;
        float prow = 0.f;
        int   rmap = 0, bidx = 0;
        if (MODE == 0) prow = aux[row];
        if (MODE == 1) { prow = g_pol[row]; rmap = g_rowmap[row]; bidx = row / NN; }
        if (MODE == 3) prow = g_pol[row];
        #pragma unroll
        for (int j = 0; j < 8; j++) {
            int col = bx * 128 + tx * 4 + ((j & 4) ? 64 : 0) + (j & 3);
            float a = acc[i][j];
            size_t oidx = (size_t)row * Nn + col;
            if (MODE == 0) {
                Cout[oidx] = a * prow;
            } else if (MODE == 1) {
                float xg = (rmap >= 0)
                    ? aux[(size_t)(bidx * NN + rmap) * CC + col] : 0.0f;
                Cout[oidx] = xg + (a + bias[col]) * prow;
            } else if (MODE == 2) {
                float tv = a + bias[col];
                Cout[oidx] = tv * 0.5f * (1.0f + erff(tv * 0.70710678118654752f));
            } else {
                Cout[oidx] = (g_x2[oidx] + a + bias[col]) * prow;
            }
        }
    }
}

// ---------------------------------------------------------------- QK^T * scale
// one block = (bh, 64x64 tile of the 197x197 score matrix); K=64 fully resident
__global__ __launch_bounds__(256)
void qk_kernel()
{
    int bh = blockIdx.x;
    int b  = bh / HH, h = bh - b * HH;
    int n0 = blockIdx.y * 64;
    int m0 = blockIdx.z * 64;

    __shared__ float Qs[64][68];   // [k][n]
    __shared__ float Ks[64][68];   // [k][m]
    int t = threadIdx.x;

    for (int e = t; e < 4096; e += 256) {
        int r = e >> 6, k = e & 63;
        int n = n0 + r;
        Qs[k][r] = (n < NN) ? g_qkv[(size_t)(b * NN + n) * C3 + h * HD + k] : 0.f;
        int m = m0 + r;
        Ks[k][r] = (m < NN) ? g_qkv[(size_t)(b * NN + m) * C3 + CC + h * HD + k] : 0.f;
    }
    __syncthreads();

    int tx = t & 15, ty = t >> 4;
    float acc[4][4];
    #pragma unroll
    for (int i = 0; i < 4; i++)
        #pragma unroll
        for (int j = 0; j < 4; j++) acc[i][j] = 0.f;

    #pragma unroll 8
    for (int k = 0; k < 64; k++) {
        float4 qa = *(const float4*)(&Qs[k][ty * 4]);
        float4 ka = *(const float4*)(&Ks[k][tx * 4]);
        float q[4] = {qa.x, qa.y, qa.z, qa.w};
        float kv[4] = {ka.x, ka.y, ka.z, ka.w};
        #pragma unroll
        for (int i = 0; i < 4; i++)
            #pragma unroll
            for (int j = 0; j < 4; j++)
                acc[i][j] = fmaf(q[i], kv[j], acc[i][j]);
    }

    #pragma unroll
    for (int i = 0; i < 4; i++) {
        int n = n0 + ty * 4 + i;
        if (n >= NN) continue;
        #pragma unroll
        for (int j = 0; j < 4; j++) {
            int m = m0 + tx * 4 + j;
            if (m < NN)
                g_attn[((size_t)bh * NN + n) * NN + m] = acc[i][j] * 0.125f;
        }
    }
}

// ---------------------------------------------------------------- softmax w/ policy + eps
// one warp per row; in-place on g_attn
__global__ void softmax_kernel(const float* __restrict__ policy)
{
    int bh = blockIdx.x;
    int n  = blockIdx.y * 8 + (threadIdx.x >> 5);
    if (n >= NN) return;
    int lane = threadIdx.x & 31;
    int b    = bh / HH;
    float* row = g_attn + ((size_t)bh * NN + n) * NN;

    float v[7];
    float mx = -1e30f;
    #pragma unroll
    for (int i = 0; i < 7; i++) {
        int m = lane + i * 32;
        v[i] = (m < NN) ? row[m] : -1e30f;
        mx = fmaxf(mx, v[i]);
    }
    #pragma unroll
    for (int o = 16; o > 0; o >>= 1) mx = fmaxf(mx, __shfl_xor_sync(0xffffffffu, mx, o));

    float s = 0.f;
    #pragma unroll
    for (int i = 0; i < 7; i++) {
        int m = lane + i * 32;
        if (m < NN) {
            float p = (m == n) ? 1.0f : policy[b * NN + m];
            v[i] = expf(v[i] - mx) * p;
            s += v[i];
        }
    }
    #pragma unroll
    for (int o = 16; o > 0; o >>= 1) s += __shfl_xor_sync(0xffffffffu, s, o);

    float inv = 1.0f / (s + 1e-6f);
    const float c = (float)(1e-6 / 197.0);
    #pragma unroll
    for (int i = 0; i < 7; i++) {
        int m = lane + i * 32;
        if (m < NN) row[m] = (v[i] + c) * inv;
    }
}

// ---------------------------------------------------------------- ATS sampling (fp64)
// one block per batch. Recomputes the CLS attention row, v-norms, scores,
// argsort, cumsum, inverse-transform picks and unique -- all in double to
// minimize deviation from the reference on the discrete decision path.
__global__ void sample_kernel(const float* __restrict__ policy)
{
    int b = blockIdx.x;
    int t = threadIdx.x;

    __shared__ double draw[NN];
    __shared__ double scacc[NN];
    __shared__ double scn[196], cdfs[196], ncdf[196];
    __shared__ int    ord[196], pick[196], spick[196], uu[196], uq[196];
    __shared__ double dred;
    __shared__ double dtmp[2];

    for (int m = t; m < NN; m += 256) scacc[m] = 0.0;
    __syncthreads();

    // smoothed CLS-row attention accumulated over heads (double)
    for (int h = 0; h < HH; h++) {
        for (int m = t; m < NN; m += 256) {
            const float* q0 = &g_qkv[(size_t)(b * NN) * C3 + h * HD];
            const float* km = &g_qkv[(size_t)(b * NN + m) * C3 + CC + h * HD];
            double s = 0.0;
            for (int d = 0; d < HD; d++) s += (double)q0[d] * (double)km[d];
            draw[m] = s * 0.125;
        }
        __syncthreads();
        if (t == 0) {
            double mx = draw[0];
            for (int m = 1; m < NN; m++) mx = (draw[m] > mx) ? draw[m] : mx;
            dred = mx;
        }
        __syncthreads();
        double mx = dred;
        for (int m = t; m < NN; m += 256) {
            double p = (m == 0) ? 1.0 : (double)policy[b * NN + m];
            draw[m] = exp(draw[m] - mx) * p;
        }
        __syncthreads();
        if (t == 0) {
            double s = 0.0;
            for (int m = 0; m < NN; m++) s += draw[m];
            dred = s + 1e-6;
        }
        __syncthreads();
        double den = dred;
        const double c = 1e-6 / 197.0;
        for (int m = t; m < NN; m += 256) scacc[m] += (draw[m] + c) / den;
        __syncthreads();
    }

    // score[j] = attn_cls_sum[j+1] * ||v[j+1]||  (double), then normalize
    for (int j = t; j < 196; j += 256) {
        int m = j + 1;
        const float* v = &g_qkv[(size_t)(b * NN + m) * C3 + 2 * CC];
        double s = 0.0;
        for (int d = 0; d < CC; d++) { double x = v[d]; s += x * x; }
        scn[j] = scacc[m] * sqrt(s);
    }
    __syncthreads();
    if (t == 0) {
        double s = 0.0;
        for (int j = 0; j < 196; j++) s += scn[j];
        dtmp[0] = s;
    }
    __syncthreads();
    double ssum = dtmp[0];
    for (int j = t; j < 196; j += 256) scn[j] = scn[j] / ssum;
    __syncthreads();

    // stable ascending argsort via rank counting
    for (int j = t; j < 196; j += 256) {
        double sj = scn[j];
        int r = 0;
        for (int i = 0; i < 196; i++) {
            double si = scn[i];
            if (si < sj || (si == sj && i < j)) r++;
        }
        ord[r] = j;
    }
    __syncthreads();

    // cdf / ncdf
    if (t == 0) {
        double c0 = 0.0;
        for (int r = 0; r < 196; r++) { c0 += scn[ord[r]]; cdfs[r] = c0; }
        double mn = cdfs[0], mx2 = cdfs[0];
        for (int r = 1; r < 196; r++) {
            double cv = cdfs[r];
            mn = cv < mn ? cv : mn;
            mx2 = cv > mx2 ? cv : mx2;
        }
        dtmp[0] = mn; dtmp[1] = mx2;
    }
    __syncthreads();
    double mn = dtmp[0], rng = dtmp[1] - dtmp[0];
    for (int r = t; r < 196; r += 256) ncdf[r] = (cdfs[r] - mn) / rng;
    __syncthreads();
    if (t == 0) {
        double ysmin = 1e18;
        for (int r = 0; r < 196; r++) {
            double v = ncdf[r] + ((ncdf[r] == 0.0) ? 1e8 : 0.0);
            ysmin = v < ysmin ? v : ysmin;
        }
        dtmp[0] = ysmin;
    }
    __syncthreads();
    double ys_start = dtmp[0];

    // inverse transform sampling: first-occurrence argmin
    for (int i = t; i < 196; i += 256) {
        double lin = (i == 195) ? 1.0 : ((double)i * (1.0 / 195.0));
        double ys  = ys_start + (lin * 195.0 - ys_start * (double)i) / 195.0;
        double best = 1e30;
        int arg = 0;
        for (int j = 0; j < 196; j++) {
            double d2 = fabs(ys - ncdf[j]);
            if (d2 < best) { best = d2; arg = j; }
        }
        pick[i] = arg;
    }
    __syncthreads();

    // sort picks ascending (stable ranks)
    for (int j = t; j < 196; j += 256) {
        int pj = pick[j];
        int r = 0;
        for (int i = 0; i < 196; i++) {
            int pi = pick[i];
            if (pi < pj || (pi == pj && i < j)) r++;
        }
        spick[r] = pj;
    }
    __syncthreads();
    // kill duplicates -> max_value (=196), literal shift-left rule
    for (int j = t; j < 196; j += 256) {
        int sl = (j < 195) ? spick[j + 1] : 1;
        uu[j] = (sl - spick[j] == 0) ? 196 : spick[j];
    }
    __syncthreads();
    // final sort
    for (int j = t; j < 196; j += 256) {
        int vj = uu[j];
        int r = 0;
        for (int i = 0; i < 196; i++) {
            int vi = uu[i];
            if (vi < vj || (vi == vj && i < j)) r++;
        }
        uq[r] = vj;
    }
    __syncthreads();

    if (t == 0) { g_rowmap[b * NN] = 0; g_pol[b * NN] = 1.0f; }
    for (int i = t; i < 196; i += 256) {
        int u = uq[i];
        g_pol[b * NN + 1 + i]    = (u != 196) ? 1.0f : 0.0f;
        g_rowmap[b * NN + 1 + i] = (u < 196) ? (1 + ord[u]) : -1;
    }
}

// ---------------------------------------------------------------- gathered attn @ V
// block = (bh, 64-row chunk of the 197 selected rows); inner K = 197 keys
__global__ __launch_bounds__(256)
void av_kernel()
{
    int bh = blockIdx.x;
    int b  = bh / HH, h = bh - b * HH;
    int n0 = blockIdx.y * 64;

    __shared__ float As[64][68];   // [k][n] gathered attn
    __shared__ float Vs[64][68];   // [k][d]
    __shared__ int   rm[64];

    int t = threadIdx.x;
    if (t < 64) {
        int n = n0 + t;
        rm[t] = (n < NN) ? g_rowmap[b * NN + n] : -1;
    }
    __syncthreads();

    int tx = t & 15, ty = t >> 4;
    float acc[4][4];
    #pragma unroll
    for (int i = 0; i < 4; i++)
        #pragma unroll
        for (int j = 0; j < 4; j++) acc[i][j] = 0.f;

    for (int m0 = 0; m0 < NN; m0 += 64) {
        for (int e = t; e < 4096; e += 256) {
            int i = e >> 6, kk = e & 63;
            int r = rm[i];
            int m = m0 + kk;
            As[kk][i] = (r >= 0 && m < NN)
                ? g_attn[((size_t)bh * NN + r) * NN + m] : 0.f;
        }
        for (int e = t; e < 4096; e += 256) {
            int kk = e >> 6, d = e & 63;
            int m = m0 + kk;
            Vs[kk][d] = (m < NN)
                ? g_qkv[(size_t)(b * NN + m) * C3 + 2 * CC + h * HD + d] : 0.f;
        }
        __syncthreads();

        #pragma unroll 8
        for (int kk = 0; kk < 64; kk++) {
            float4 aa4 = *(const float4*)(&As[kk][ty * 4]);
            float4 vv4 = *(const float4*)(&Vs[kk][tx * 4]);
            float aa[4] = {aa4.x, aa4.y, aa4.z, aa4.w};
            float vv[4] = {vv4.x, vv4.y, vv4.z, vv4.w};
            #pragma unroll
            for (int i = 0; i < 4; i++)
                #pragma unroll
                for (int j = 0; j < 4; j++)
                    acc[i][j] = fmaf(aa[i], vv[j], acc[i][j]);
        }
        __syncthreads();
    }

    #pragma unroll
    for (int i = 0; i < 4; i++) {
        int n = n0 + ty * 4 + i;
        if (n >= NN) continue;
        #pragma unroll
        for (int j = 0; j < 4; j++)
            g_xo[(size_t)(b * NN + n) * CC + h * HD + tx * 4 + j] = acc[i][j];
    }
}

// ---------------------------------------------------------------- launch
extern "C" void kernel_launch(void* const* d_in, const int* in_sizes, int n_in,
                              void* d_out, int out_size)
{
    const float* x      = (const float*)d_in[0];
    const float* policy = (const float*)d_in[1];
    const float* w_qkv  = (const float*)d_in[2];
    const float* w_proj = (const float*)d_in[3];
    const float* b_proj = (const float*)d_in[4];
    const float* g1     = (const float*)d_in[5];
    const float* b1     = (const float*)d_in[6];
    const float* g2     = (const float*)d_in[7];
    const float* b2     = (const float*)d_in[8];
    const float* w_fc1  = (const float*)d_in[9];
    const float* b_fc1  = (const float*)d_in[10];
    const float* w_fc2  = (const float*)d_in[11];
    const float* b_fc2  = (const float*)d_in[12];
    float* out = (float*)d_out;

    const int MTILES = (MR + 127) / 128;   // 99

    // 1. LN1
    ln_kernel<<<MR, 256>>>(x, g1, b1, 0);
    // 2. QKV GEMM (+ policy epilogue)
    sgemm_k<0><<<dim3(C3 / 128, MTILES), 256>>>(w_qkv, nullptr, policy, nullptr);
    // 3. Q K^T * scale
    qk_kernel<<<dim3(BH, 4, 4), 256>>>();
    // 4. softmax with policy + eps smoothing (in place)
    softmax_kernel<<<dim3(BH, 25), 256>>>(policy);
    // 5. ATS sampling (fp64 critical path) -> rowmap / pol
    sample_kernel<<<BB, 256>>>(policy);
    // 6. gathered attn @ V
    av_kernel<<<dim3(BH, 4), 256>>>();
    // 7. proj GEMM (+ bias, *pol, + gathered x residual) -> x2
    sgemm_k<1><<<dim3(CC / 128, MTILES), 256>>>(w_proj, b_proj, x, nullptr);
    // 8. LN2
    ln_kernel<<<MR, 256>>>(nullptr, g2, b2, 1);
    // 9. FC1 GEMM + exact GELU
    sgemm_k<2><<<dim3(C4 / 128, MTILES), 256>>>(w_fc1, b_fc1, nullptr, nullptr);
    // 10. FC2 GEMM + residual + *pol -> out
    sgemm_k<3><<<dim3(CC / 128, MTILES), 256>>>(w_fc2, b_fc2, nullptr, out);
}

// round 10
// speedup vs baseline: 1.5498x; 1.5498x over previous
#include <cuda_runtime.h>
#include <math.h>
#include <stdint.h>

// ---------------------------------------------------------------- constants
#define BB 64
#define NN 197
#define CC 768
#define HH 12
#define HD 64
#define C3 2304
#define C4 3072
#define MR (BB*NN)        /* 12608 rows */
#define BH (BB*HH)        /* 768 (b,h) pairs */
#define LN_EPS 1e-5f

// ---------------------------------------------------------------- scratch
__device__ __align__(16) float g_xn  [(size_t)MR * CC];
__device__ __align__(16) float g_qkv [(size_t)MR * C3];
__device__ __align__(16) float g_attn[(size_t)BH * NN * NN];
__device__ __align__(16) float g_xo  [(size_t)MR * CC];
__device__ __align__(16) float g_x2  [(size_t)MR * CC];
__device__ __align__(16) float g_ln2 [(size_t)MR * CC];
__device__ __align__(16) float g_fc1 [(size_t)MR * C4];
__device__ int   g_rowmap[MR];
__device__ float g_pol   [MR];

// ---------------------------------------------------------------- helpers
__device__ __forceinline__ uint32_t f2tf32(float x) {
    uint32_t u;
    asm("cvt.rna.tf32.f32 %0, %1;" : "=r"(u) : "f"(x));
    return u;
}

// ---------------------------------------------------------------- LayerNorm
__global__ void ln_kernel(const float* __restrict__ Xin,
                          const float* __restrict__ gam,
                          const float* __restrict__ bet,
                          int mode)
{
    const float* X = (mode == 0) ? Xin : g_x2;
    float*       Y = (mode == 0) ? g_xn : g_ln2;

    __shared__ float red[40];
    int row = blockIdx.x;
    int t   = threadIdx.x;
    const float* x = X + (size_t)row * CC;

    float v0 = x[t], v1 = x[t + 256], v2 = x[t + 512];

    float s = v0 + v1 + v2;
    #pragma unroll
    for (int o = 16; o > 0; o >>= 1) s += __shfl_xor_sync(0xffffffffu, s, o);
    if ((t & 31) == 0) red[t >> 5] = s;
    __syncthreads();
    if (t < 32) {
        float r = (t < 8) ? red[t] : 0.0f;
        #pragma unroll
        for (int o = 4; o > 0; o >>= 1) r += __shfl_xor_sync(0xffffffffu, r, o);
        if (t == 0) red[32] = r;
    }
    __syncthreads();
    float mean = red[32] * (1.0f / 768.0f);
    __syncthreads();

    float d0 = v0 - mean, d1 = v1 - mean, d2 = v2 - mean;
    s = d0 * d0 + d1 * d1 + d2 * d2;
    #pragma unroll
    for (int o = 16; o > 0; o >>= 1) s += __shfl_xor_sync(0xffffffffu, s, o);
    if ((t & 31) == 0) red[t >> 5] = s;
    __syncthreads();
    if (t < 32) {
        float r = (t < 8) ? red[t] : 0.0f;
        #pragma unroll
        for (int o = 4; o > 0; o >>= 1) r += __shfl_xor_sync(0xffffffffu, r, o);
        if (t == 0) red[33] = r;
    }
    __syncthreads();
    float var  = red[33] * (1.0f / 768.0f);
    float rstd = 1.0f / sqrtf(var + LN_EPS);

    float* y = Y + (size_t)row * CC;
    y[t]       = d0 * rstd * gam[t]       + bet[t];
    y[t + 256] = d1 * rstd * gam[t + 256] + bet[t + 256];
    y[t + 512] = d2 * rstd * gam[t + 512] + bet[t + 512];
}

// ---------------------------------------------------------------- fp32 SGEMM (QKV only)
// g_xn @ w_qkv(768x2304) -> g_qkv ; epilogue: * policy[row]
// Stays fp32: qkv feeds the discrete sampling path (pick-flip risk with TF32).
__global__ __launch_bounds__(256)
void sgemm_qkv(const float* __restrict__ Bm, const float* __restrict__ policy)
{
    const int Nn = C3, Kk = CC;
    const float* A = g_xn;
    float* Cout = g_qkv;

    __shared__ float As[16][128];
    __shared__ float Bs[16][128];

    int tid  = threadIdx.x;
    int bx   = blockIdx.x;
    int row0 = blockIdx.y * 128;
    int tx   = tid & 15;
    int ty   = tid >> 4;

    int a_r = tid >> 2;
    int a_c = (tid & 3) << 2;
    int b_r = tid >> 5;
    int b_c = (tid & 31) << 2;

    float acc[8][8];
    #pragma unroll
    for (int i = 0; i < 8; i++)
        #pragma unroll
        for (int j = 0; j < 8; j++) acc[i][j] = 0.0f;

    for (int k0 = 0; k0 < Kk; k0 += 16) {
        #pragma unroll
        for (int p = 0; p < 2; p++) {
            int r = row0 + a_r + p * 64;
            float4 v = (r < MR)
                ? *(const float4*)(A + (size_t)r * Kk + k0 + a_c)
                : make_float4(0.f, 0.f, 0.f, 0.f);
            As[a_c + 0][a_r + p * 64] = v.x;
            As[a_c + 1][a_r + p * 64] = v.y;
            As[a_c + 2][a_r + p * 64] = v.z;
            As[a_c + 3][a_r + p * 64] = v.w;
        }
        #pragma unroll
        for (int p = 0; p < 2; p++) {
            int kr = k0 + b_r + p * 8;
            *(float4*)(&Bs[b_r + p * 8][b_c]) =
                *(const float4*)(Bm + (size_t)kr * Nn + bx * 128 + b_c);
        }
        __syncthreads();

        #pragma unroll
        for (int k = 0; k < 16; k++) {
            float af[8], bf[8];
            *(float4*)(af)     = *(const float4*)(&As[k][ty * 4]);
            *(float4*)(af + 4) = *(const float4*)(&As[k][ty * 4 + 64]);
            *(float4*)(bf)     = *(const float4*)(&Bs[k][tx * 4]);
            *(float4*)(bf + 4) = *(const float4*)(&Bs[k][tx * 4 + 64]);
            #pragma unroll
            for (int i = 0; i < 8; i++)
                #pragma unroll
                for (int j = 0; j < 8; j++)
                    acc[i][j] = fmaf(af[i], bf[j], acc[i][j]);
        }
        __syncthreads();
    }

    #pragma unroll
    for (int i = 0; i < 8; i++) {
        int row = row0 + ty * 4 + ((i & 4) ? 64 : 0) + (i & 3);
        if (row >= MR) continue;
        float prow = policy[row];
        #pragma unroll
        for (int j = 0; j < 8; j++) {
            int col = bx * 128 + tx * 4 + ((j & 4) ? 64 : 0) + (j & 3);
            Cout[(size_t)row * Nn + col] = acc[i][j] * prow;
        }
    }
}

// ---------------------------------------------------------------- TF32 tensor-core GEMM
// MODE 1: g_xo  @ Bm(768x768)  -> g_x2  ; epi: xgather + (acc+b)*pol  (aux = x)
// MODE 2: g_ln2 @ Bm(768x3072) -> g_fc1 ; epi: exact GELU(acc+b)
// MODE 3: g_fc1 @ Bm(3072x768) -> Cext  ; epi: (g_x2 + acc + b)*pol
// 128x128x32 tile, 8 warps x (64x32) warp tiles, mma.m16n8k8 tf32 (cvt.rna inputs).
template <int MODE>
__global__ __launch_bounds__(256, 2)
void tf32_gemm(const float* __restrict__ Bm,
               const float* __restrict__ bias,
               const float* __restrict__ aux,
               float* __restrict__ Cext)
{
    constexpr int Nn = (MODE == 2) ? C4 : CC;
    constexpr int Kk = (MODE == 3) ? C4 : CC;
    const float* A = (MODE == 1) ? g_xo : (MODE == 2) ? g_ln2 : g_fc1;
    float* Cout    = (MODE == 1) ? g_x2 : (MODE == 2) ? g_fc1 : Cext;

    __shared__ uint32_t As[128][36];   // [m][k], bank map 4*fr+fc : conflict-free
    __shared__ uint32_t Bs[32][136];   // [k][n], bank map 8*k +n  : conflict-free

    int tid  = threadIdx.x;
    int lane = tid & 31;
    int wid  = tid >> 5;
    int bx   = blockIdx.x;
    int row0 = blockIdx.y * 128;

    int wm = (wid & 1) * 64;   // warp M offset
    int wn = (wid >> 1) * 32;  // warp N offset
    int fr = lane >> 2;        // 0..7
    int fc = lane & 3;         // 0..3

    float acc[4][4][4];
    #pragma unroll
    for (int i = 0; i < 4; i++)
        #pragma unroll
        for (int j = 0; j < 4; j++)
            #pragma unroll
            for (int q = 0; q < 4; q++) acc[i][j][q] = 0.0f;

    for (int k0 = 0; k0 < Kk; k0 += 32) {
        // A tile: 128 rows x 32 k  (8 float4 per row)
        #pragma unroll
        for (int p = 0; p < 4; p++) {
            int idx = tid + p * 256;
            int r   = idx >> 3;
            int c   = (idx & 7) << 2;
            int gr  = row0 + r;
            float4 v = (gr < MR)
                ? *(const float4*)(A + (size_t)gr * Kk + k0 + c)
                : make_float4(0.f, 0.f, 0.f, 0.f);
            As[r][c + 0] = f2tf32(v.x);
            As[r][c + 1] = f2tf32(v.y);
            As[r][c + 2] = f2tf32(v.z);
            As[r][c + 3] = f2tf32(v.w);
        }
        // B tile: 32 k-rows x 128 n
        #pragma unroll
        for (int p = 0; p < 4; p++) {
            int idx = tid + p * 256;
            int kr  = idx >> 5;
            int c   = (idx & 31) << 2;
            float4 v = *(const float4*)(Bm + (size_t)(k0 + kr) * Nn + bx * 128 + c);
            Bs[kr][c + 0] = f2tf32(v.x);
            Bs[kr][c + 1] = f2tf32(v.y);
            Bs[kr][c + 2] = f2tf32(v.z);
            Bs[kr][c + 3] = f2tf32(v.w);
        }
        __syncthreads();

        #pragma unroll
        for (int sub = 0; sub < 4; sub++) {
            int kb = sub * 8;
            uint32_t a[4][4], b[4][2];
            #pragma unroll
            for (int i = 0; i < 4; i++) {
                int mr = wm + i * 16 + fr;
                a[i][0] = As[mr    ][kb + fc    ];
                a[i][1] = As[mr + 8][kb + fc    ];
                a[i][2] = As[mr    ][kb + fc + 4];
                a[i][3] = As[mr + 8][kb + fc + 4];
            }
            #pragma unroll
            for (int j = 0; j < 4; j++) {
                int nc = wn + j * 8 + fr;
                b[j][0] = Bs[kb + fc    ][nc];
                b[j][1] = Bs[kb + fc + 4][nc];
            }
            #pragma unroll
            for (int i = 0; i < 4; i++)
                #pragma unroll
                for (int j = 0; j < 4; j++)
                    asm volatile(
                        "mma.sync.aligned.m16n8k8.row.col.f32.tf32.tf32.f32 "
                        "{%0,%1,%2,%3}, {%4,%5,%6,%7}, {%8,%9}, {%0,%1,%2,%3};"
                        : "+f"(acc[i][j][0]), "+f"(acc[i][j][1]),
                          "+f"(acc[i][j][2]), "+f"(acc[i][j][3])
                        : "r"(a[i][0]), "r"(a[i][1]), "r"(a[i][2]), "r"(a[i][3]),
                          "r"(b[j][0]), "r"(b[j][1]));
        }
        __syncthreads();
    }

    // epilogue: c0,c1 at (row, col..col+1); c2,c3 at (row+8, col..col+1)
    #pragma unroll
    for (int i = 0; i < 4; i++) {
        #pragma unroll
        for (int half = 0; half < 2; half++) {
            int row = row0 + wm + i * 16 + fr + half * 8;
            if (row >= MR) continue;
            float prow = 0.f;
            int   rmap = 0, bidx = 0;
            if (MODE == 1) { prow = g_pol[row]; rmap = g_rowmap[row]; bidx = row / NN; }
            if (MODE == 3) prow = g_pol[row];
            #pragma unroll
            for (int j = 0; j < 4; j++) {
                #pragma unroll
                for (int q = 0; q < 2; q++) {
                    int col = bx * 128 + wn + j * 8 + 2 * fc + q;
                    float a = acc[i][j][half * 2 + q];
                    size_t oidx = (size_t)row * Nn + col;
                    if (MODE == 1) {
                        float xg = (rmap >= 0)
                            ? aux[(size_t)(bidx * NN + rmap) * CC + col] : 0.0f;
                        Cout[oidx] = xg + (a + bias[col]) * prow;
                    } else if (MODE == 2) {
                        float tv = a + bias[col];
                        Cout[oidx] = tv * 0.5f * (1.0f + erff(tv * 0.70710678118654752f));
                    } else {
                        Cout[oidx] = (g_x2[oidx] + a + bias[col]) * prow;
                    }
                }
            }
        }
    }
}

// ---------------------------------------------------------------- QK^T * scale
__global__ __launch_bounds__(256)
void qk_kernel()
{
    int bh = blockIdx.x;
    int b  = bh / HH, h = bh - b * HH;
    int n0 = blockIdx.y * 64;
    int m0 = blockIdx.z * 64;

    __shared__ float Qs[64][68];
    __shared__ float Ks[64][68];
    int t = threadIdx.x;

    for (int e = t; e < 4096; e += 256) {
        int r = e >> 6, k = e & 63;
        int n = n0 + r;
        Qs[k][r] = (n < NN) ? g_qkv[(size_t)(b * NN + n) * C3 + h * HD + k] : 0.f;
        int m = m0 + r;
        Ks[k][r] = (m < NN) ? g_qkv[(size_t)(b * NN + m) * C3 + CC + h * HD + k] : 0.f;
    }
    __syncthreads();

    int tx = t & 15, ty = t >> 4;
    float acc[4][4];
    #pragma unroll
    for (int i = 0; i < 4; i++)
        #pragma unroll
        for (int j = 0; j < 4; j++) acc[i][j] = 0.f;

    #pragma unroll 8
    for (int k = 0; k < 64; k++) {
        float4 qa = *(const float4*)(&Qs[k][ty * 4]);
        float4 ka = *(const float4*)(&Ks[k][tx * 4]);
        float q[4] = {qa.x, qa.y, qa.z, qa.w};
        float kv[4] = {ka.x, ka.y, ka.z, ka.w};
        #pragma unroll
        for (int i = 0; i < 4; i++)
            #pragma unroll
            for (int j = 0; j < 4; j++)
                acc[i][j] = fmaf(q[i], kv[j], acc[i][j]);
    }

    #pragma unroll
    for (int i = 0; i < 4; i++) {
        int n = n0 + ty * 4 + i;
        if (n >= NN) continue;
        #pragma unroll
        for (int j = 0; j < 4; j++) {
            int m = m0 + tx * 4 + j;
            if (m < NN)
                g_attn[((size_t)bh * NN + n) * NN + m] = acc[i][j] * 0.125f;
        }
    }
}

// ---------------------------------------------------------------- softmax w/ policy + eps
__global__ void softmax_kernel(const float* __restrict__ policy)
{
    int bh = blockIdx.x;
    int n  = blockIdx.y * 8 + (threadIdx.x >> 5);
    if (n >= NN) return;
    int lane = threadIdx.x & 31;
    int b    = bh / HH;
    float* row = g_attn + ((size_t)bh * NN + n) * NN;

    float v[7];
    float mx = -1e30f;
    #pragma unroll
    for (int i = 0; i < 7; i++) {
        int m = lane + i * 32;
        v[i] = (m < NN) ? row[m] : -1e30f;
        mx = fmaxf(mx, v[i]);
    }
    #pragma unroll
    for (int o = 16; o > 0; o >>= 1) mx = fmaxf(mx, __shfl_xor_sync(0xffffffffu, mx, o));

    float s = 0.f;
    #pragma unroll
    for (int i = 0; i < 7; i++) {
        int m = lane + i * 32;
        if (m < NN) {
            float p = (m == n) ? 1.0f : policy[b * NN + m];
            v[i] = expf(v[i] - mx) * p;
            s += v[i];
        }
    }
    #pragma unroll
    for (int o = 16; o > 0; o >>= 1) s += __shfl_xor_sync(0xffffffffu, s, o);

    float inv = 1.0f / (s + 1e-6f);
    const float c = (float)(1e-6 / 197.0);
    #pragma unroll
    for (int i = 0; i < 7; i++) {
        int m = lane + i * 32;
        if (m < NN) row[m] = (v[i] + c) * inv;
    }
}

// ---------------------------------------------------------------- ATS sampling (fp64)
__global__ void sample_kernel(const float* __restrict__ policy)
{
    int b = blockIdx.x;
    int t = threadIdx.x;

    __shared__ double draw[NN];
    __shared__ double scacc[NN];
    __shared__ double scn[196], cdfs[196], ncdf[196];
    __shared__ int    ord[196], pick[196], spick[196], uu[196], uq[196];
    __shared__ double dred;
    __shared__ double dtmp[2];

    for (int m = t; m < NN; m += 256) scacc[m] = 0.0;
    __syncthreads();

    for (int h = 0; h < HH; h++) {
        for (int m = t; m < NN; m += 256) {
            const float* q0 = &g_qkv[(size_t)(b * NN) * C3 + h * HD];
            const float* km = &g_qkv[(size_t)(b * NN + m) * C3 + CC + h * HD];
            double s = 0.0;
            for (int d = 0; d < HD; d++) s += (double)q0[d] * (double)km[d];
            draw[m] = s * 0.125;
        }
        __syncthreads();
        if (t == 0) {
            double mx = draw[0];
            for (int m = 1; m < NN; m++) mx = (draw[m] > mx) ? draw[m] : mx;
            dred = mx;
        }
        __syncthreads();
        double mx = dred;
        for (int m = t; m < NN; m += 256) {
            double p = (m == 0) ? 1.0 : (double)policy[b * NN + m];
            draw[m] = exp(draw[m] - mx) * p;
        }
        __syncthreads();
        if (t == 0) {
            double s = 0.0;
            for (int m = 0; m < NN; m++) s += draw[m];
            dred = s + 1e-6;
        }
        __syncthreads();
        double den = dred;
        const double c = 1e-6 / 197.0;
        for (int m = t; m < NN; m += 256) scacc[m] += (draw[m] + c) / den;
        __syncthreads();
    }

    for (int j = t; j < 196; j += 256) {
        int m = j + 1;
        const float* v = &g_qkv[(size_t)(b * NN + m) * C3 + 2 * CC];
        double s = 0.0;
        for (int d = 0; d < CC; d++) { double x = v[d]; s += x * x; }
        scn[j] = scacc[m] * sqrt(s);
    }
    __syncthreads();
    if (t == 0) {
        double s = 0.0;
        for (int j = 0; j < 196; j++) s += scn[j];
        dtmp[0] = s;
    }
    __syncthreads();
    double ssum = dtmp[0];
    for (int j = t; j < 196; j += 256) scn[j] = scn[j] / ssum;
    __syncthreads();

    for (int j = t; j < 196; j += 256) {
        double sj = scn[j];
        int r = 0;
        for (int i = 0; i < 196; i++) {
            double si = scn[i];
            if (si < sj || (si == sj && i < j)) r++;
        }
        ord[r] = j;
    }
    __syncthreads();

    if (t == 0) {
        double c0 = 0.0;
        for (int r = 0; r < 196; r++) { c0 += scn[ord[r]]; cdfs[r] = c0; }
        double mn = cdfs[0], mx2 = cdfs[0];
        for (int r = 1; r < 196; r++) {
            double cv = cdfs[r];
            mn = cv < mn ? cv : mn;
            mx2 = cv > mx2 ? cv : mx2;
        }
        dtmp[0] = mn; dtmp[1] = mx2;
    }
    __syncthreads();
    double mn = dtmp[0], rng = dtmp[1] - dtmp[0];
    for (int r = t; r < 196; r += 256) ncdf[r] = (cdfs[r] - mn) / rng;
    __syncthreads();
    if (t == 0) {
        double ysmin = 1e18;
        for (int r = 0; r < 196; r++) {
            double v = ncdf[r] + ((ncdf[r] == 0.0) ? 1e8 : 0.0);
            ysmin = v < ysmin ? v : ysmin;
        }
        dtmp[0] = ysmin;
    }
    __syncthreads();
    double ys_start = dtmp[0];

    for (int i = t; i < 196; i += 256) {
        double lin = (i == 195) ? 1.0 : ((double)i * (1.0 / 195.0));
        double ys  = ys_start + (lin * 195.0 - ys_start * (double)i) / 195.0;
        double best = 1e30;
        int arg = 0;
        for (int j = 0; j < 196; j++) {
            double d2 = fabs(ys - ncdf[j]);
            if (d2 < best) { best = d2; arg = j; }
        }
        pick[i] = arg;
    }
    __syncthreads();

    for (int j = t; j < 196; j += 256) {
        int pj = pick[j];
        int r = 0;
        for (int i = 0; i < 196; i++) {
            int pi = pick[i];
            if (pi < pj || (pi == pj && i < j)) r++;
        }
        spick[r] = pj;
    }
    __syncthreads();
    for (int j = t; j < 196; j += 256) {
        int sl = (j < 195) ? spick[j + 1] : 1;
        uu[j] = (sl - spick[j] == 0) ? 196 : spick[j];
    }
    __syncthreads();
    for (int j = t; j < 196; j += 256) {
        int vj = uu[j];
        int r = 0;
        for (int i = 0; i < 196; i++) {
            int vi = uu[i];
            if (vi < vj || (vi == vj && i < j)) r++;
        }
        uq[r] = vj;
    }
    __syncthreads();

    if (t == 0) { g_rowmap[b * NN] = 0; g_pol[b * NN] = 1.0f; }
    for (int i = t; i < 196; i += 256) {
        int u = uq[i];
        g_pol[b * NN + 1 + i]    = (u != 196) ? 1.0f : 0.0f;
        g_rowmap[b * NN + 1 + i] = (u < 196) ? (1 + ord[u]) : -1;
    }
}

// ---------------------------------------------------------------- gathered attn @ V
__global__ __launch_bounds__(256)
void av_kernel()
{
    int bh = blockIdx.x;
    int b  = bh / HH, h = bh - b * HH;
    int n0 = blockIdx.y * 64;

    __shared__ float As[64][68];
    __shared__ float Vs[64][68];
    __shared__ int   rm[64];

    int t = threadIdx.x;
    if (t < 64) {
        int n = n0 + t;
        rm[t] = (n < NN) ? g_rowmap[b * NN + n] : -1;
    }
    __syncthreads();

    int tx = t & 15, ty = t >> 4;
    float acc[4][4];
    #pragma unroll
    for (int i = 0; i < 4; i++)
        #pragma unroll
        for (int j = 0; j < 4; j++) acc[i][j] = 0.f;

    for (int m0 = 0; m0 < NN; m0 += 64) {
        for (int e = t; e < 4096; e += 256) {
            int i = e >> 6, kk = e & 63;
            int r = rm[i];
            int m = m0 + kk;
            As[kk][i] = (r >= 0 && m < NN)
                ? g_attn[((size_t)bh * NN + r) * NN + m] : 0.f;
        }
        for (int e = t; e < 4096; e += 256) {
            int kk = e >> 6, d = e & 63;
            int m = m0 + kk;
            Vs[kk][d] = (m < NN)
                ? g_qkv[(size_t)(b * NN + m) * C3 + 2 * CC + h * HD + d] : 0.f;
        }
        __syncthreads();

        #pragma unroll 8
        for (int kk = 0; kk < 64; kk++) {
            float4 aa4 = *(const float4*)(&As[kk][ty * 4]);
            float4 vv4 = *(const float4*)(&Vs[kk][tx * 4]);
            float aa[4] = {aa4.x, aa4.y, aa4.z, aa4.w};
            float vv[4] = {vv4.x, vv4.y, vv4.z, vv4.w};
            #pragma unroll
            for (int i = 0; i < 4; i++)
                #pragma unroll
                for (int j = 0; j < 4; j++)
                    acc[i][j] = fmaf(aa[i], vv[j], acc[i][j]);
        }
        __syncthreads();
    }

    #pragma unroll
    for (int i = 0; i < 4; i++) {
        int n = n0 + ty * 4 + i;
        if (n >= NN) continue;
        #pragma unroll
        for (int j = 0; j < 4; j++)
            g_xo[(size_t)(b * NN + n) * CC + h * HD + tx * 4 + j] = acc[i][j];
    }
}

// ---------------------------------------------------------------- launch
extern "C" void kernel_launch(void* const* d_in, const int* in_sizes, int n_in,
                              void* d_out, int out_size)
{
    const float* x      = (const float*)d_in[0];
    const float* policy = (const float*)d_in[1];
    const float* w_qkv  = (const float*)d_in[2];
    const float* w_proj = (const float*)d_in[3];
    const float* b_proj = (const float*)d_in[4];
    const float* g1     = (const float*)d_in[5];
    const float* b1     = (const float*)d_in[6];
    const float* g2     = (const float*)d_in[7];
    const float* b2     = (const float*)d_in[8];
    const float* w_fc1  = (const float*)d_in[9];
    const float* b_fc1  = (const float*)d_in[10];
    const float* w_fc2  = (const float*)d_in[11];
    const float* b_fc2  = (const float*)d_in[12];
    float* out = (float*)d_out;

    const int MTILES = (MR + 127) / 128;   // 99

    // 1. LN1
    ln_kernel<<<MR, 256>>>(x, g1, b1, 0);
    // 2. QKV GEMM (fp32 — feeds the discrete sampling path)
    sgemm_qkv<<<dim3(C3 / 128, MTILES), 256>>>(w_qkv, policy);
    // 3. Q K^T * scale
    qk_kernel<<<dim3(BH, 4, 4), 256>>>();
    // 4. softmax with policy + eps smoothing (in place)
    softmax_kernel<<<dim3(BH, 25), 256>>>(policy);
    // 5. ATS sampling (fp64 critical path) -> rowmap / pol
    sample_kernel<<<BB, 256>>>(policy);
    // 6. gathered attn @ V
    av_kernel<<<dim3(BH, 4), 256>>>();
    // 7. proj GEMM (TF32 TC) + bias, *pol, + gathered x residual -> x2
    tf32_gemm<1><<<dim3(CC / 128, MTILES), 256>>>(w_proj, b_proj, x, nullptr);
    // 8. LN2
    ln_kernel<<<MR, 256>>>(nullptr, g2, b2, 1);
    // 9. FC1 GEMM (TF32 TC) + exact GELU
    tf32_gemm<2><<<dim3(C4 / 128, MTILES), 256>>>(w_fc1, b_fc1, nullptr, nullptr);
    // 10. FC2 GEMM (TF32 TC) + residual + *pol -> out
    tf32_gemm<3><<<dim3(CC / 128, MTILES), 256>>>(w_fc2, b_fc2, nullptr, out);
}